// round 8
// baseline (speedup 1.0000x reference)
#include <cuda_runtime.h>
#include <cuda_fp16.h>
#include <cstdint>
#include <cstddef>

// ---------------------------------------------------------------------------
// Problem constants
// ---------------------------------------------------------------------------
#define T_STEPS 2048
#define BATCH   256
#define IN_DIM  64
#define H_DIM   1280
#define H4      320
#define HID     160
#define GATES   640      // 4*HID
#define O_DIM   32

#define MTOT    (T_STEPS*BATCH)   // 524288
#define CHUNK   65536             // rows per GEMM chunk (8 chunks)

// ---------------------------------------------------------------------------
// Scratch (device globals — no allocation allowed)
// ---------------------------------------------------------------------------
__device__ __align__(256) float gX1c[(size_t)CHUNK * H_DIM];   // 335 MB
__device__ __align__(256) float gX2c[(size_t)CHUNK * H4];      //  84 MB
__device__ __align__(256) float gGX [(size_t)MTOT  * GATES];   // 1.34 GB
__device__ __align__(256) float gHout[(size_t)MTOT * HID];     // 335 MB
__device__ __align__(256) uint2 gWt2[40 * GATES];              // W_hh packed fp16

// ---------------------------------------------------------------------------
// Packed fp32x2 FMA (sm_103a)
// ---------------------------------------------------------------------------
__device__ __forceinline__ float2 ffma2(float2 a, float2 b, float2 c) {
    float2 d;
    asm("fma.rn.f32x2 %0, %1, %2, %3;"
        : "=l"(reinterpret_cast<unsigned long long&>(d))
        : "l"(reinterpret_cast<unsigned long long&>(a)),
          "l"(reinterpret_cast<unsigned long long&>(b)),
          "l"(reinterpret_cast<unsigned long long&>(c)));
    return d;
}

__device__ __forceinline__ float fast_sigmoid(float x) {
    return __fdividef(1.f, 1.f + __expf(-x));
}
__device__ __forceinline__ float fast_tanh(float x) {
    return 1.f - __fdividef(2.f, __expf(2.f * x) + 1.f);
}

// ---------------------------------------------------------------------------
// SGEMM:  C[m][n] = act( sum_k A[m][k] * W[n][k] + bias[n] (+ bias2[n]) )
// Tile: BM=128, BN=64, BK=16, 128 threads, 8x8 per-thread via f32x2.
// Requires M%128==0, N%64==0, K%16==0.
// ---------------------------------------------------------------------------
template <int ACT>   // 0 = identity, 1 = leaky_relu(0.01)
__global__ __launch_bounds__(128)
void sgemm_tn(const float* __restrict__ A, const float* __restrict__ W,
              const float* __restrict__ bias, const float* __restrict__ bias2,
              float* __restrict__ C, int M, int N, int K)
{
    __shared__ float As[16][128];
    __shared__ float Bs[16][64];

    const int tid = threadIdx.x;
    const int m0  = blockIdx.y * 128;
    const int n0  = blockIdx.x * 64;
    const int ty  = tid >> 3;        // 0..15
    const int tx  = tid & 7;         // 0..7
    const int ar  = tid >> 2;        // 0..31
    const int ak  = (tid & 3) << 2;  // 0,4,8,12

    float2 acc[8][4];
#pragma unroll
    for (int i = 0; i < 8; ++i)
#pragma unroll
        for (int j = 0; j < 4; ++j) acc[i][j] = make_float2(0.f, 0.f);

    for (int k0 = 0; k0 < K; k0 += 16) {
#pragma unroll
        for (int i = 0; i < 4; ++i) {
            int row = ar + i * 32;
            float4 v = *(const float4*)(A + (size_t)(m0 + row) * K + k0 + ak);
            As[ak + 0][row] = v.x; As[ak + 1][row] = v.y;
            As[ak + 2][row] = v.z; As[ak + 3][row] = v.w;
        }
#pragma unroll
        for (int i = 0; i < 2; ++i) {
            int idx = tid + i * 128;
            int n   = idx >> 2;
            int kq  = (idx & 3) << 2;
            float4 v = *(const float4*)(W + (size_t)(n0 + n) * K + k0 + kq);
            Bs[kq + 0][n] = v.x; Bs[kq + 1][n] = v.y;
            Bs[kq + 2][n] = v.z; Bs[kq + 3][n] = v.w;
        }
        __syncthreads();

#pragma unroll
        for (int k = 0; k < 16; ++k) {
            float4 a0 = *(const float4*)&As[k][ty * 8];
            float4 a1 = *(const float4*)&As[k][ty * 8 + 4];
            float4 b0 = *(const float4*)&Bs[k][tx * 8];
            float4 b1 = *(const float4*)&Bs[k][tx * 8 + 4];
            float2 bb[4] = { make_float2(b0.x, b0.y), make_float2(b0.z, b0.w),
                             make_float2(b1.x, b1.y), make_float2(b1.z, b1.w) };
            float av[8]  = { a0.x, a0.y, a0.z, a0.w, a1.x, a1.y, a1.z, a1.w };
#pragma unroll
            for (int i = 0; i < 8; ++i) {
                float2 as2 = make_float2(av[i], av[i]);
#pragma unroll
                for (int j = 0; j < 4; ++j)
                    acc[i][j] = ffma2(as2, bb[j], acc[i][j]);
            }
        }
        __syncthreads();
    }

    float bv[8];
#pragma unroll
    for (int j = 0; j < 8; ++j) {
        bv[j] = bias[n0 + tx * 8 + j];
        if (bias2) bv[j] += bias2[n0 + tx * 8 + j];
    }
#pragma unroll
    for (int i = 0; i < 8; ++i) {
        size_t row = (size_t)(m0 + ty * 8 + i);
        float o[8];
#pragma unroll
        for (int j = 0; j < 4; ++j) {
            o[2*j]   = acc[i][j].x + bv[2*j];
            o[2*j+1] = acc[i][j].y + bv[2*j+1];
        }
        if (ACT) {
#pragma unroll
            for (int j = 0; j < 8; ++j) o[j] = (o[j] > 0.f) ? o[j] : 0.01f * o[j];
        }
        float4 v0 = make_float4(o[0], o[1], o[2], o[3]);
        float4 v1 = make_float4(o[4], o[5], o[6], o[7]);
        *(float4*)(C + row * N + n0 + tx * 8)     = v0;
        *(float4*)(C + row * N + n0 + tx * 8 + 4) = v1;
    }
}

// ---------------------------------------------------------------------------
// Prepack W_hh [640][160] fp32 -> gWt2[p][g] = 4 consecutive-k fp16 weights,
// gate-major-inner so the scan's LDS is conflict-free.
// ---------------------------------------------------------------------------
__global__ void prepack_whh(const float* __restrict__ W)
{
    int i = blockIdx.x * 256 + threadIdx.x;
    if (i >= 40 * GATES) return;
    int p = i / GATES, g = i % GATES;
    const float* wr = W + (size_t)g * HID + p * 4;
    __half2 h01 = __floats2half2_rn(wr[0], wr[1]);
    __half2 h23 = __floats2half2_rn(wr[2], wr[3]);
    uint2 v;
    v.x = *reinterpret_cast<uint32_t*>(&h01);
    v.y = *reinterpret_cast<uint32_t*>(&h23);
    gWt2[(size_t)p * GATES + g] = v;
}

// ---------------------------------------------------------------------------
// Persistent LSTM scan: 128 CTAs x 640 threads, 2 batch rows per CTA.
// W_hh fp16 in SMEM, fp32 accumulate via FFMA2 over the 2-row pair.
// Writes h history to gHout; y is a separate GEMM afterwards.
// ---------------------------------------------------------------------------
#define SCAN_SMEM (40 * GATES * 8 + 2 * HID * 4 + 2 * GATES * 4)  // 211200 B

__global__ __launch_bounds__(GATES, 1)
void lstm_scan(const float* __restrict__ GX, float* __restrict__ Hout)
{
    extern __shared__ unsigned char smem_raw[];
    uint2* sW = reinterpret_cast<uint2*>(smem_raw);                 // [40][640]
    float* sH = reinterpret_cast<float*>(smem_raw + 40 * GATES * 8); // [2][160]
    float* sG = sH + 2 * HID;                                        // [2][640]

    const int tid  = threadIdx.x;
    const int g    = tid;
    const int row0 = blockIdx.x * 2;

    // Load W_hh (fp16) into SMEM
    for (int i = tid; i < 40 * GATES; i += GATES) sW[i] = gWt2[i];
    if (tid < 2 * HID) sH[tid] = 0.f;

    float cc = 0.f;                 // cell carry for tid<320: row=tid/160, j=tid%160
    const int cr = tid < 2 * HID ? (tid / HID) : 0;
    const int cj = tid < 2 * HID ? (tid - cr * HID) : 0;

    __syncthreads();

    for (int t = 0; t < T_STEPS; ++t) {
        const size_t base = (size_t)t * (BATCH * GATES) + (size_t)row0 * GATES;
        float gx0 = GX[base + g];
        float gx1 = GX[base + GATES + g];

        float2 acc0 = make_float2(0.f, 0.f);
        float2 acc1 = make_float2(0.f, 0.f);
#pragma unroll
        for (int p = 0; p < 40; ++p) {
            uint2 w = sW[p * GATES + g];
            float2 wA = __half22float2(*reinterpret_cast<__half2*>(&w.x));
            float2 wB = __half22float2(*reinterpret_cast<__half2*>(&w.y));
            float4 h0v = *reinterpret_cast<const float4*>(&sH[p * 4]);
            float4 h1v = *reinterpret_cast<const float4*>(&sH[HID + p * 4]);
            acc0 = ffma2(wA, make_float2(h0v.x, h0v.y), acc0);
            acc0 = ffma2(wB, make_float2(h0v.z, h0v.w), acc0);
            acc1 = ffma2(wA, make_float2(h1v.x, h1v.y), acc1);
            acc1 = ffma2(wB, make_float2(h1v.z, h1v.w), acc1);
        }
        float p0 = acc0.x + acc0.y + gx0;
        float p1 = acc1.x + acc1.y + gx1;

        // gate order: [0,160)=i  [160,320)=f  [320,480)=g  [480,640)=o
        float a0, a1;
        if (g >= 320 && g < 480) { a0 = fast_tanh(p0);    a1 = fast_tanh(p1);    }
        else                     { a0 = fast_sigmoid(p0); a1 = fast_sigmoid(p1); }
        sG[g] = a0;
        sG[GATES + g] = a1;
        __syncthreads();

        if (tid < 2 * HID) {
            const float* Gr = sG + cr * GATES;
            float iv = Gr[cj], fv = Gr[HID + cj], gv = Gr[2 * HID + cj], ov = Gr[3 * HID + cj];
            cc = fv * cc + iv * gv;
            float hv = ov * fast_tanh(cc);
            sH[cr * HID + cj] = hv;
            Hout[(size_t)t * (BATCH * HID) + (size_t)(row0 + cr) * HID + cj] = hv;
        }
        __syncthreads();
    }
}

// ---------------------------------------------------------------------------
// Output projection: Y[m][o] = H[m] . W3[o] + b3[o]    (M x 32, K=160)
// block = 256 threads = 8 rows x 32 outputs
// ---------------------------------------------------------------------------
__global__ __launch_bounds__(256)
void out_gemv(const float* __restrict__ H, const float* __restrict__ W3,
              const float* __restrict__ b3, float* __restrict__ Y)
{
    __shared__ float sW[HID * O_DIM];   // transposed [k][o]
    __shared__ float sHr[8 * HID];

    const int tid = threadIdx.x;
    const int r   = tid >> 5;          // 0..7
    const int o   = tid & 31;

    for (int i = tid; i < HID * O_DIM; i += 256) {
        int k = i >> 5, oo = i & 31;
        sW[i] = W3[(size_t)oo * HID + k];
    }
    const size_t mrow0 = (size_t)blockIdx.x * 8;
    for (int i = tid; i < 8 * HID; i += 256)
        sHr[i] = H[mrow0 * HID + i];
    __syncthreads();

    float acc = b3[o];
#pragma unroll 8
    for (int k = 0; k < HID; ++k)
        acc = fmaf(sHr[r * HID + k], sW[k * O_DIM + o], acc);
    Y[(mrow0 + r) * O_DIM + o] = acc;
}

// ---------------------------------------------------------------------------
// Launch
// ---------------------------------------------------------------------------
extern "C" void kernel_launch(void* const* d_in, const int* in_sizes, int n_in,
                              void* d_out, int out_size)
{
    (void)in_sizes; (void)n_in; (void)out_size;
    const float* inputs = (const float*)d_in[0];
    const float* W1     = (const float*)d_in[1];
    const float* b1     = (const float*)d_in[2];
    const float* W2     = (const float*)d_in[3];
    const float* b2     = (const float*)d_in[4];
    const float* W_ih   = (const float*)d_in[5];
    const float* W_hh   = (const float*)d_in[6];
    const float* b_ih   = (const float*)d_in[7];
    const float* b_hh   = (const float*)d_in[8];
    const float* W3     = (const float*)d_in[9];
    const float* b3     = (const float*)d_in[10];
    float* Y = (float*)d_out;

    void *pX1, *pX2, *pGX, *pH;
    cudaGetSymbolAddress(&pX1, gX1c);
    cudaGetSymbolAddress(&pX2, gX2c);
    cudaGetSymbolAddress(&pGX, gGX);
    cudaGetSymbolAddress(&pH,  gHout);
    float* X1 = (float*)pX1;
    float* X2 = (float*)pX2;
    float* GX = (float*)pGX;
    float* Hh = (float*)pH;

    cudaFuncSetAttribute(lstm_scan, cudaFuncAttributeMaxDynamicSharedMemorySize,
                         SCAN_SMEM);

    // Chunked fc1 -> fc2 -> x-side gates
    for (int c = 0; c < MTOT / CHUNK; ++c) {
        const float* Ain = inputs + (size_t)c * CHUNK * IN_DIM;
        sgemm_tn<1><<<dim3(H_DIM / 64, CHUNK / 128), 128>>>(
            Ain, W1, b1, nullptr, X1, CHUNK, H_DIM, IN_DIM);
        sgemm_tn<1><<<dim3(H4 / 64, CHUNK / 128), 128>>>(
            X1, W2, b2, nullptr, X2, CHUNK, H4, H_DIM);
        sgemm_tn<0><<<dim3(GATES / 64, CHUNK / 128), 128>>>(
            X2, W_ih, b_ih, b_hh, GX + (size_t)c * CHUNK * GATES,
            CHUNK, GATES, H4);
    }

    // Pack W_hh and run the recurrence
    prepack_whh<<<(40 * GATES + 255) / 256, 256>>>(W_hh);
    lstm_scan<<<BATCH / 2, GATES, SCAN_SMEM>>>(GX, Hh);

    // Output projection
    out_gemv<<<MTOT / 8, 256>>>(Hh, W3, b3, Y);
}

// round 12
// speedup vs baseline: 1.9222x; 1.9222x over previous
#include <cuda_runtime.h>
#include <cuda_fp16.h>
#include <cuda_bf16.h>
#include <cstdint>
#include <cstddef>

// ---------------------------------------------------------------------------
// Problem constants
// ---------------------------------------------------------------------------
#define T_STEPS 2048
#define BATCH   256
#define IN_DIM  64
#define H_DIM   1280
#define H4      320
#define HID     160
#define GATES   640
#define O_DIM   32
#define MTOT    (T_STEPS*BATCH)   // 524288
#define CHUNK   65536             // rows per pipeline chunk (8 chunks)

// ---------------------------------------------------------------------------
// Device scratch — keep total under ~2.5GB (aarch64 .bss shadow reloc limit)
// ---------------------------------------------------------------------------
__device__ __align__(256) __nv_bfloat16 gIhi [(size_t)CHUNK * IN_DIM];
__device__ __align__(256) __nv_bfloat16 gIlo [(size_t)CHUNK * IN_DIM];
__device__ __align__(256) __nv_bfloat16 gX1hi[(size_t)CHUNK * H_DIM];
__device__ __align__(256) __nv_bfloat16 gX1lo[(size_t)CHUNK * H_DIM];
__device__ __align__(256) __nv_bfloat16 gX2hi[(size_t)CHUNK * H4];
__device__ __align__(256) __nv_bfloat16 gX2lo[(size_t)CHUNK * H4];
__device__ __align__(256) float gGX  [(size_t)MTOT * GATES];            // 1.34GB
__device__ __align__(256) float gHout[(size_t)MTOT * HID];              // 335MB
__device__ __align__(256) __nv_bfloat16 gW1hi[H_DIM * IN_DIM];
__device__ __align__(256) __nv_bfloat16 gW1lo[H_DIM * IN_DIM];
__device__ __align__(256) __nv_bfloat16 gW2hi[H4 * H_DIM];
__device__ __align__(256) __nv_bfloat16 gW2lo[H4 * H_DIM];
__device__ __align__(256) __nv_bfloat16 gWihi[GATES * H4];
__device__ __align__(256) __nv_bfloat16 gWilo[GATES * H4];
__device__ __align__(256) uint2 gWt2[40 * GATES];   // W_hh fp16 pack for scan

// ---------------------------------------------------------------------------
// PTX helpers — base-ISA only (sm_80+ features, legal on .target sm_103)
// ---------------------------------------------------------------------------
__device__ __forceinline__ uint32_t smem_u32(const void* p) {
    uint32_t a;
    asm("{ .reg .u64 t; cvta.to.shared.u64 t, %1; cvt.u32.u64 %0, t; }"
        : "=r"(a) : "l"(p));
    return a;
}
__device__ __forceinline__ void cp_async16(uint32_t dst, const void* src) {
    asm volatile("cp.async.cg.shared.global [%0], [%1], 16;"
                 :: "r"(dst), "l"(src) : "memory");
}
#define CP_COMMIT() asm volatile("cp.async.commit_group;" ::: "memory")
#define CP_WAIT(n)  asm volatile("cp.async.wait_group %0;" :: "n"(n) : "memory")

__device__ __forceinline__ void ldsm_x4(uint32_t* r, uint32_t addr) {
    asm volatile("ldmatrix.sync.aligned.m8n8.x4.shared.b16 {%0,%1,%2,%3}, [%4];"
        : "=r"(r[0]), "=r"(r[1]), "=r"(r[2]), "=r"(r[3]) : "r"(addr));
}
__device__ __forceinline__ void mma16816(float* d, const uint32_t* a,
                                         const uint32_t* b) {
    asm volatile("mma.sync.aligned.m16n8k16.row.col.f32.bf16.bf16.f32 "
        "{%0,%1,%2,%3}, {%4,%5,%6,%7}, {%8,%9}, {%0,%1,%2,%3};"
        : "+f"(d[0]), "+f"(d[1]), "+f"(d[2]), "+f"(d[3])
        : "r"(a[0]), "r"(a[1]), "r"(a[2]), "r"(a[3]), "r"(b[0]), "r"(b[1]));
}

// ---------------------------------------------------------------------------
// SMEM layout for mma_gemm (dynamic, 49664 B)
//   buf b (b=0,1) at b*24576:
//     Ahi [128][32]bf16 @+0 (8K), Alo @+8192, Bhi [64][32] @+16384 (4K), Blo @+20480
//   stage (epilogue, union with buffers): float [128][72] = 36864 B @0
//   sBias: 64 floats @49152
// Swizzle: 16B chunk index c (0..3) of row -> c ^ ((row>>1)&3). Conflict-free
// for ldmatrix (8 distinct 16B slots per phase) and cp.async stores.
// ---------------------------------------------------------------------------
#define GEMM_SMEM 49664

template <int OUTMODE>   // 0: leaky -> bf16 hi/lo planes; 1: fp32 out (+bias2)
__global__ __launch_bounds__(256, 2)
void mma_gemm(const __nv_bfloat16* __restrict__ Ahi, const __nv_bfloat16* __restrict__ Alo,
              const __nv_bfloat16* __restrict__ Bhi, const __nv_bfloat16* __restrict__ Blo,
              const float* __restrict__ bias, const float* __restrict__ bias2,
              __nv_bfloat16* __restrict__ outHi, __nv_bfloat16* __restrict__ outLo,
              float* __restrict__ outF, int N, int K)
{
    extern __shared__ __align__(128) char smem[];
    const uint32_t sbase = smem_u32(smem);
    const int tid  = threadIdx.x;
    const int lane = tid & 31;
    const int w    = tid >> 5;
    const int warpM = w & 3;        // 0..3 -> M rows [warpM*32, +32)
    const int warpN = w >> 2;       // 0..1 -> N cols [warpN*32, +32)
    const int m0 = blockIdx.y * 128;
    const int n0 = blockIdx.x * 64;

    float* sBias = (float*)(smem + 49152);
    if (tid < 64) {
        float bv = bias[n0 + tid];
        if (bias2) bv += bias2[n0 + tid];
        sBias[tid] = bv;
    }

    float acc[2][4][4];
#pragma unroll
    for (int mt = 0; mt < 2; ++mt)
#pragma unroll
        for (int nt = 0; nt < 4; ++nt)
#pragma unroll
            for (int r = 0; r < 4; ++r) acc[mt][nt][r] = 0.f;

    const int NK = K >> 5;

    // Per-lane ldmatrix offsets (within a buffer).
    // A (x4): lanes 0-7 rows r0..r0+7 @k-octet s*2   -> a0 (rows 0-7,  k 0-7)
    //         lanes 8-15 rows r0+8..15 @k-octet s*2  -> a1 (rows 8-15, k 0-7)
    //         lanes 16-23 rows r0..7 @octet s*2+1    -> a2 (rows 0-7,  k 8-15)
    //         lanes 24-31 rows r0+8..15 @s*2+1       -> a3 (rows 8-15, k 8-15)
    uint32_t offA[2][2], offB[2][2];
#pragma unroll
    for (int mt = 0; mt < 2; ++mt)
#pragma unroll
        for (int s = 0; s < 2; ++s) {
            int row = warpM * 32 + mt * 16 + (lane & 15);
            int ch  = s * 2 + (lane >> 4);
            offA[mt][s] = row * 64 + ((ch ^ ((row >> 1) & 3)) << 4);
        }
    // B (x4, NON-trans; B smem is [N][K] so each reg = 2 consecutive k @ fixed n):
    //   group g = lane>>3:  g0: n0..7 @octet s*2   -> t0 = (n 0-7,  k 0-7)
    //                       g1: n0..7 @s*2+1       -> t1 = (n 0-7,  k 8-15)
    //                       g2: n8..15 @s*2        -> t2 = (n 8-15, k 0-7)
    //                       g3: n8..15 @s*2+1      -> t3 = (n 8-15, k 8-15)
#pragma unroll
    for (int nh = 0; nh < 2; ++nh)
#pragma unroll
        for (int s = 0; s < 2; ++s) {
            int g   = lane >> 3;
            int row = warpN * 32 + nh * 16 + ((g >> 1) << 3) + (lane & 7);
            int ch  = s * 2 + (g & 1);
            offB[nh][s] = 16384 + row * 64 + ((ch ^ ((row >> 1) & 3)) << 4);
        }

    auto issue_load = [&](int kt) {
        const uint32_t bb = sbase + (uint32_t)(kt & 1) * 24576;
        const size_t kof = (size_t)kt * 32;
#pragma unroll
        for (int j = 0; j < 4; ++j) {           // A: 1024 16B-chunks
            int i = tid + j * 256;
            int plane = i >> 9, row = (i >> 2) & 127, c = i & 3;
            const __nv_bfloat16* src =
                (plane ? Alo : Ahi) + (size_t)(m0 + row) * K + kof + c * 8;
            uint32_t dst = bb + plane * 8192 + row * 64 +
                           ((c ^ ((row >> 1) & 3)) << 4);
            cp_async16(dst, src);
        }
#pragma unroll
        for (int j = 0; j < 2; ++j) {           // B: 512 16B-chunks
            int i = tid + j * 256;
            int plane = i >> 8, row = (i >> 2) & 63, c = i & 3;
            const __nv_bfloat16* src =
                (plane ? Blo : Bhi) + (size_t)(n0 + row) * K + kof + c * 8;
            uint32_t dst = bb + 16384 + plane * 4096 + row * 64 +
                           ((c ^ ((row >> 1) & 3)) << 4);
            cp_async16(dst, src);
        }
        CP_COMMIT();
    };

    issue_load(0);

    for (int kt = 0; kt < NK; ++kt) {
        const uint32_t bb = sbase + (uint32_t)(kt & 1) * 24576;
        if (kt + 1 < NK) { issue_load(kt + 1); CP_WAIT(1); }
        else             { CP_WAIT(0); }
        __syncthreads();

#pragma unroll
        for (int s = 0; s < 2; ++s) {
            uint32_t ah[2][4], al[2][4], bh[4][2], bl[4][2];
#pragma unroll
            for (int mt = 0; mt < 2; ++mt) {
                ldsm_x4(ah[mt], bb + offA[mt][s]);
                ldsm_x4(al[mt], bb + 8192 + offA[mt][s]);
            }
#pragma unroll
            for (int nh = 0; nh < 2; ++nh) {
                uint32_t t[4];
                ldsm_x4(t, bb + offB[nh][s]);               // hi plane (no trans!)
                bh[nh*2][0]   = t[0]; bh[nh*2][1]   = t[1];
                bh[nh*2+1][0] = t[2]; bh[nh*2+1][1] = t[3];
                ldsm_x4(t, bb + 4096 + offB[nh][s]);        // lo plane
                bl[nh*2][0]   = t[0]; bl[nh*2][1]   = t[1];
                bl[nh*2+1][0] = t[2]; bl[nh*2+1][1] = t[3];
            }
#pragma unroll
            for (int mt = 0; mt < 2; ++mt)
#pragma unroll
                for (int nt = 0; nt < 4; ++nt) {
                    mma16816(acc[mt][nt], ah[mt], bh[nt]);
                    mma16816(acc[mt][nt], ah[mt], bl[nt]);
                    mma16816(acc[mt][nt], al[mt], bh[nt]);
                }
        }
        __syncthreads();
    }

    // ---------------- Epilogue: stage fp32 [128][72], then fused writeout ---
    float* stage = (float*)smem;
#pragma unroll
    for (int mt = 0; mt < 2; ++mt)
#pragma unroll
        for (int nt = 0; nt < 4; ++nt) {
            int r = warpM * 32 + mt * 16 + (lane >> 2);
            int c = warpN * 32 + nt * 8 + (lane & 3) * 2;
            stage[r * 72 + c]           = acc[mt][nt][0];
            stage[r * 72 + c + 1]       = acc[mt][nt][1];
            stage[(r + 8) * 72 + c]     = acc[mt][nt][2];
            stage[(r + 8) * 72 + c + 1] = acc[mt][nt][3];
        }
    __syncthreads();

    if (OUTMODE == 0) {
#pragma unroll
        for (int j = 0; j < 16; ++j) {
            int i = tid + j * 256;              // 0..4095 (row, col-pair)
            int r = i >> 5, cp = i & 31;
            float v0 = stage[r * 72 + cp * 2]     + sBias[cp * 2];
            float v1 = stage[r * 72 + cp * 2 + 1] + sBias[cp * 2 + 1];
            v0 = (v0 > 0.f) ? v0 : 0.01f * v0;
            v1 = (v1 > 0.f) ? v1 : 0.01f * v1;
            __nv_bfloat16 h0 = __float2bfloat16(v0);
            __nv_bfloat16 h1 = __float2bfloat16(v1);
            __nv_bfloat16 l0 = __float2bfloat16(v0 - __bfloat162float(h0));
            __nv_bfloat16 l1 = __float2bfloat16(v1 - __bfloat162float(h1));
            __nv_bfloat162 hp = {h0, h1};
            __nv_bfloat162 lp = {l0, l1};
            size_t base = ((size_t)(m0 + r) * N + n0) >> 1;
            ((uint32_t*)outHi)[base + cp] = *(uint32_t*)&hp;
            ((uint32_t*)outLo)[base + cp] = *(uint32_t*)&lp;
        }
    } else {
#pragma unroll
        for (int j = 0; j < 32; ++j) {
            int i = tid + j * 256;              // 0..8191
            int r = i >> 6, c = i & 63;
            outF[(size_t)(m0 + r) * N + n0 + c] = stage[r * 72 + c] + sBias[c];
        }
    }
}

// ---------------------------------------------------------------------------
// fp32 -> bf16 hi/lo split (vectorized x4)
// ---------------------------------------------------------------------------
__global__ void split_bf16(const float* __restrict__ src,
                           __nv_bfloat16* __restrict__ hi,
                           __nv_bfloat16* __restrict__ lo, long n4)
{
    long i = (long)blockIdx.x * 256 + threadIdx.x;
    if (i >= n4) return;
    float4 v = ((const float4*)src)[i];
    float vs[4] = {v.x, v.y, v.z, v.w};
    __nv_bfloat16 h[4], l[4];
#pragma unroll
    for (int k = 0; k < 4; ++k) {
        h[k] = __float2bfloat16(vs[k]);
        l[k] = __float2bfloat16(vs[k] - __bfloat162float(h[k]));
    }
    *(uint2*)(hi + i * 4) = *(uint2*)h;
    *(uint2*)(lo + i * 4) = *(uint2*)l;
}

// ---------------------------------------------------------------------------
// Scan prep + scan + output GEMV (unchanged from the passing R8 kernel)
// ---------------------------------------------------------------------------
__device__ __forceinline__ float2 ffma2(float2 a, float2 b, float2 c) {
    float2 d;
    asm("fma.rn.f32x2 %0, %1, %2, %3;"
        : "=l"(reinterpret_cast<unsigned long long&>(d))
        : "l"(reinterpret_cast<unsigned long long&>(a)),
          "l"(reinterpret_cast<unsigned long long&>(b)),
          "l"(reinterpret_cast<unsigned long long&>(c)));
    return d;
}
__device__ __forceinline__ float fast_sigmoid(float x) {
    return __fdividef(1.f, 1.f + __expf(-x));
}
__device__ __forceinline__ float fast_tanh(float x) {
    return 1.f - __fdividef(2.f, __expf(2.f * x) + 1.f);
}

__global__ void prepack_whh(const float* __restrict__ W)
{
    int i = blockIdx.x * 256 + threadIdx.x;
    if (i >= 40 * GATES) return;
    int p = i / GATES, g = i % GATES;
    const float* wr = W + (size_t)g * HID + p * 4;
    __half2 h01 = __floats2half2_rn(wr[0], wr[1]);
    __half2 h23 = __floats2half2_rn(wr[2], wr[3]);
    uint2 v;
    v.x = *reinterpret_cast<uint32_t*>(&h01);
    v.y = *reinterpret_cast<uint32_t*>(&h23);
    gWt2[(size_t)p * GATES + g] = v;
}

#define SCAN_SMEM (40 * GATES * 8 + 2 * HID * 4 + 2 * GATES * 4)

__global__ __launch_bounds__(GATES, 1)
void lstm_scan(const float* __restrict__ GX, float* __restrict__ Hout)
{
    extern __shared__ unsigned char smem_raw[];
    uint2* sW = reinterpret_cast<uint2*>(smem_raw);
    float* sH = reinterpret_cast<float*>(smem_raw + 40 * GATES * 8);
    float* sG = sH + 2 * HID;

    const int tid  = threadIdx.x;
    const int g    = tid;
    const int row0 = blockIdx.x * 2;

    for (int i = tid; i < 40 * GATES; i += GATES) sW[i] = gWt2[i];
    if (tid < 2 * HID) sH[tid] = 0.f;

    float cc = 0.f;
    const int cr = tid < 2 * HID ? (tid / HID) : 0;
    const int cj = tid < 2 * HID ? (tid - cr * HID) : 0;

    __syncthreads();

    for (int t = 0; t < T_STEPS; ++t) {
        const size_t base = (size_t)t * (BATCH * GATES) + (size_t)row0 * GATES;
        float gx0 = GX[base + g];
        float gx1 = GX[base + GATES + g];

        float2 acc0 = make_float2(0.f, 0.f);
        float2 acc1 = make_float2(0.f, 0.f);
#pragma unroll
        for (int p = 0; p < 40; ++p) {
            uint2 w = sW[p * GATES + g];
            float2 wA = __half22float2(*reinterpret_cast<__half2*>(&w.x));
            float2 wB = __half22float2(*reinterpret_cast<__half2*>(&w.y));
            float4 h0v = *reinterpret_cast<const float4*>(&sH[p * 4]);
            float4 h1v = *reinterpret_cast<const float4*>(&sH[HID + p * 4]);
            acc0 = ffma2(wA, make_float2(h0v.x, h0v.y), acc0);
            acc0 = ffma2(wB, make_float2(h0v.z, h0v.w), acc0);
            acc1 = ffma2(wA, make_float2(h1v.x, h1v.y), acc1);
            acc1 = ffma2(wB, make_float2(h1v.z, h1v.w), acc1);
        }
        float p0 = acc0.x + acc0.y + gx0;
        float p1 = acc1.x + acc1.y + gx1;

        float a0, a1;
        if (g >= 320 && g < 480) { a0 = fast_tanh(p0);    a1 = fast_tanh(p1);    }
        else                     { a0 = fast_sigmoid(p0); a1 = fast_sigmoid(p1); }
        sG[g] = a0;
        sG[GATES + g] = a1;
        __syncthreads();

        if (tid < 2 * HID) {
            const float* Gr = sG + cr * GATES;
            float iv = Gr[cj], fv = Gr[HID + cj], gv = Gr[2 * HID + cj], ov = Gr[3 * HID + cj];
            cc = fv * cc + iv * gv;
            float hv = ov * fast_tanh(cc);
            sH[cr * HID + cj] = hv;
            Hout[(size_t)t * (BATCH * HID) + (size_t)(row0 + cr) * HID + cj] = hv;
        }
        __syncthreads();
    }
}

__global__ __launch_bounds__(256)
void out_gemv(const float* __restrict__ H, const float* __restrict__ W3,
              const float* __restrict__ b3, float* __restrict__ Y)
{
    __shared__ float sW[HID * O_DIM];
    __shared__ float sHr[8 * HID];

    const int tid = threadIdx.x;
    const int r   = tid >> 5;
    const int o   = tid & 31;

    for (int i = tid; i < HID * O_DIM; i += 256) {
        int k = i >> 5, oo = i & 31;
        sW[i] = W3[(size_t)oo * HID + k];
    }
    const size_t mrow0 = (size_t)blockIdx.x * 8;
    for (int i = tid; i < 8 * HID; i += 256)
        sHr[i] = H[mrow0 * HID + i];
    __syncthreads();

    float acc = b3[o];
#pragma unroll 8
    for (int k = 0; k < HID; ++k)
        acc = fmaf(sHr[r * HID + k], sW[k * O_DIM + o], acc);
    Y[(mrow0 + r) * O_DIM + o] = acc;
}

// ---------------------------------------------------------------------------
// Launch
// ---------------------------------------------------------------------------
extern "C" void kernel_launch(void* const* d_in, const int* in_sizes, int n_in,
                              void* d_out, int out_size)
{
    (void)in_sizes; (void)n_in; (void)out_size;
    const float* inputs = (const float*)d_in[0];
    const float* W1     = (const float*)d_in[1];
    const float* b1     = (const float*)d_in[2];
    const float* W2     = (const float*)d_in[3];
    const float* b2     = (const float*)d_in[4];
    const float* W_ih   = (const float*)d_in[5];
    const float* W_hh   = (const float*)d_in[6];
    const float* b_ih   = (const float*)d_in[7];
    const float* b_hh   = (const float*)d_in[8];
    const float* W3     = (const float*)d_in[9];
    const float* b3     = (const float*)d_in[10];
    float* Y = (float*)d_out;

    void *pIh, *pIl, *pX1h, *pX1l, *pX2h, *pX2l, *pGX, *pH;
    void *pW1h, *pW1l, *pW2h, *pW2l, *pWih, *pWil;
    cudaGetSymbolAddress(&pIh,  gIhi);  cudaGetSymbolAddress(&pIl,  gIlo);
    cudaGetSymbolAddress(&pX1h, gX1hi); cudaGetSymbolAddress(&pX1l, gX1lo);
    cudaGetSymbolAddress(&pX2h, gX2hi); cudaGetSymbolAddress(&pX2l, gX2lo);
    cudaGetSymbolAddress(&pGX,  gGX);   cudaGetSymbolAddress(&pH,   gHout);
    cudaGetSymbolAddress(&pW1h, gW1hi); cudaGetSymbolAddress(&pW1l, gW1lo);
    cudaGetSymbolAddress(&pW2h, gW2hi); cudaGetSymbolAddress(&pW2l, gW2lo);
    cudaGetSymbolAddress(&pWih, gWihi); cudaGetSymbolAddress(&pWil, gWilo);

    cudaFuncSetAttribute(mma_gemm<0>, cudaFuncAttributeMaxDynamicSharedMemorySize, GEMM_SMEM);
    cudaFuncSetAttribute(mma_gemm<1>, cudaFuncAttributeMaxDynamicSharedMemorySize, GEMM_SMEM);
    cudaFuncSetAttribute(lstm_scan, cudaFuncAttributeMaxDynamicSharedMemorySize, SCAN_SMEM);

    // Split weights into bf16 hi/lo planes (once)
    split_bf16<<<H_DIM * IN_DIM / 4 / 256, 256>>>(W1,
        (__nv_bfloat16*)pW1h, (__nv_bfloat16*)pW1l, H_DIM * IN_DIM / 4);
    split_bf16<<<H4 * H_DIM / 4 / 256, 256>>>(W2,
        (__nv_bfloat16*)pW2h, (__nv_bfloat16*)pW2l, H4 * H_DIM / 4);
    split_bf16<<<GATES * H4 / 4 / 256, 256>>>(W_ih,
        (__nv_bfloat16*)pWih, (__nv_bfloat16*)pWil, GATES * H4 / 4);

    // Chunked batch-parallel pipeline: input split -> fc1 -> fc2 -> gates
    for (int c = 0; c < MTOT / CHUNK; ++c) {
        const float* Ain = inputs + (size_t)c * CHUNK * IN_DIM;
        split_bf16<<<(long)CHUNK * IN_DIM / 4 / 256, 256>>>(Ain,
            (__nv_bfloat16*)pIh, (__nv_bfloat16*)pIl, (long)CHUNK * IN_DIM / 4);

        mma_gemm<0><<<dim3(H_DIM / 64, CHUNK / 128), 256, GEMM_SMEM>>>(
            (__nv_bfloat16*)pIh, (__nv_bfloat16*)pIl,
            (__nv_bfloat16*)pW1h, (__nv_bfloat16*)pW1l,
            b1, nullptr,
            (__nv_bfloat16*)pX1h, (__nv_bfloat16*)pX1l, nullptr, H_DIM, IN_DIM);

        mma_gemm<0><<<dim3(H4 / 64, CHUNK / 128), 256, GEMM_SMEM>>>(
            (__nv_bfloat16*)pX1h, (__nv_bfloat16*)pX1l,
            (__nv_bfloat16*)pW2h, (__nv_bfloat16*)pW2l,
            b2, nullptr,
            (__nv_bfloat16*)pX2h, (__nv_bfloat16*)pX2l, nullptr, H4, H_DIM);

        mma_gemm<1><<<dim3(GATES / 64, CHUNK / 128), 256, GEMM_SMEM>>>(
            (__nv_bfloat16*)pX2h, (__nv_bfloat16*)pX2l,
            (__nv_bfloat16*)pWih, (__nv_bfloat16*)pWil,
            b_ih, b_hh,
            nullptr, nullptr, (float*)pGX + (size_t)c * CHUNK * GATES,
            GATES, H4);
    }

    // Recurrence + output projection
    prepack_whh<<<(40 * GATES + 255) / 256, 256>>>(W_hh);
    lstm_scan<<<BATCH / 2, GATES, SCAN_SMEM>>>((float*)pGX, (float*)pH);
    out_gemv<<<MTOT / 8, 256>>>((float*)pH, W3, b3, Y);
}